// round 5
// baseline (speedup 1.0000x reference)
#include <cuda_runtime.h>
#include <math.h>

#define NUM_EMB 512
#define DIM 64
#define NPTS 131072          // 32*64*64 spatial points
#define TPB 256
#define NBLK (NPTS / TPB)    // 512 blocks
#define HW 4096              // 64*64

// Output layout (fp32): [loss(1) | quantized NCHW(8388608) | perplexity(1) | encodings(131072*512)]
#define Q_ELEMS 8388608
#define FULL_OUT 75497474

// Scratch (no allocations allowed)
__device__ float g_partial[NBLK];
__device__ int   g_hist[NUM_EMB];

// ---------------- f32x2 helpers (FFMA2 path, sm_100+) ----------------
__device__ __forceinline__ unsigned long long pack2(float lo, float hi) {
    unsigned long long r;
    asm("mov.b64 %0, {%1, %2};" : "=l"(r) : "f"(lo), "f"(hi));
    return r;
}
__device__ __forceinline__ void unpack2(unsigned long long v, float& lo, float& hi) {
    asm("mov.b64 {%0, %1}, %2;" : "=f"(lo), "=f"(hi) : "l"(v));
}
__device__ __forceinline__ void fma2(unsigned long long& acc, unsigned long long a, unsigned long long b) {
    asm("fma.rn.f32x2 %0, %1, %2, %0;" : "+l"(acc) : "l"(a), "l"(b));
}
__device__ __forceinline__ unsigned long long add2(unsigned long long a, unsigned long long b) {
    unsigned long long r;
    asm("add.rn.f32x2 %0, %1, %2;" : "=l"(r) : "l"(a), "l"(b));
    return r;
}

// ---------------- init: zero the histogram ----------------
__global__ void vq_init() {
    int t = threadIdx.x;
    if (t < NUM_EMB) g_hist[t] = 0;
}

// ---------------- main kernel ----------------
// SMEM layout:
//   s_ep  : 256 code-pairs * 64 dims * 8B = 131072 B  (interleaved (e[2k][i], e[2k+1][i]))
//   s_hn  : 256 * 8B = 2048 B                        ((-0.5||e_2k||^2, -0.5||e_2k+1||^2))
//   s_kmin: 256 * 4B
//   s_red : 256 * 4B
#define SMEM_BYTES (131072 + 2048 + 1024 + 1024)

extern __shared__ unsigned char s_raw[];

__global__ __launch_bounds__(TPB, 1)
void vq_main(const float* __restrict__ x,
             const float* __restrict__ emb,
             float* __restrict__ out_q,
             float* __restrict__ out_enc,
             int write_aux) {
    unsigned long long* s_ep = (unsigned long long*)s_raw;   // 256*64
    unsigned long long* s_hn = s_ep + 256 * 64;              // 256
    int*   s_kmin = (int*)(s_hn + 256);                      // 256
    float* s_red  = (float*)(s_kmin + TPB);                  // 256

    const int tid = threadIdx.x;

    // ---- cooperative fill of code-pair table ----
    for (int idx = tid; idx < 256 * 64; idx += TPB) {
        int k2 = idx >> 6, i = idx & 63;
        float a = emb[(k2 * 2) * DIM + i];
        float b = emb[(k2 * 2 + 1) * DIM + i];
        s_ep[idx] = pack2(a, b);
    }
    __syncthreads();

    // ---- per-pair half-norms ----
    {
        float n0 = 0.f, n1 = 0.f;
        const unsigned long long* row = s_ep + tid * 64;
        #pragma unroll 8
        for (int i = 0; i < 64; i++) {
            float a, b; unpack2(row[i], a, b);
            n0 += a * a; n1 += b * b;
        }
        s_hn[tid] = pack2(-0.5f * n0, -0.5f * n1);
    }

    // ---- load this thread's point z (channel-strided gather, coalesced per channel) ----
    const int n = blockIdx.x * TPB + tid;
    const int base = ((n >> 12) << 18) + (n & (HW - 1));   // b*262144 + h*64 + w
    unsigned long long zp[DIM];
    #pragma unroll
    for (int d = 0; d < DIM; d++) {
        float zv = x[base + (d << 12)];
        zp[d] = pack2(zv, zv);
    }
    __syncthreads();

    // ---- argmax over s_k = z.e_k - 0.5||e_k||^2  (== argmin distance; tie -> lowest index) ----
    float best = -3.4e38f;
    int bestk = 0;
    for (int k2 = 0; k2 < 256; ++k2) {
        const ulonglong2* e2 = (const ulonglong2*)(s_ep + k2 * 64);
        unsigned long long a0 = s_hn[k2], a1 = 0ull, a2 = 0ull, a3 = 0ull;
        #pragma unroll
        for (int i = 0; i < 16; i++) {
            ulonglong2 v0 = e2[2 * i];
            ulonglong2 v1 = e2[2 * i + 1];
            fma2(a0, zp[4 * i + 0], v0.x);
            fma2(a1, zp[4 * i + 1], v0.y);
            fma2(a2, zp[4 * i + 2], v1.x);
            fma2(a3, zp[4 * i + 3], v1.y);
        }
        unsigned long long s = add2(add2(a0, a1), add2(a2, a3));
        float s0, s1; unpack2(s, s0, s1);
        if (s0 > best) { best = s0; bestk = 2 * k2; }
        if (s1 > best) { best = s1; bestk = 2 * k2 + 1; }
    }

    s_kmin[tid] = bestk;
    atomicAdd(&g_hist[bestk], 1);   // integer atomics: order-invariant -> deterministic

    // ---- quantized scatter (coalesced per channel) + commitment-loss partial ----
    float lsum = 0.f;
    {
        const unsigned long long* erow = s_ep + (bestk >> 1) * 64;
        const int odd = bestk & 1;
        #pragma unroll 8
        for (int d = 0; d < DIM; d++) {
            float a, b; unpack2(erow[d], a, b);
            float e = odd ? b : a;
            float zv, zhi; unpack2(zp[d], zv, zhi);
            float diff = e - zv;
            lsum += diff * diff;
            out_q[base + (d << 12)] = e;
        }
    }

    // ---- deterministic fixed-order block reduction of loss partials ----
    s_red[tid] = lsum;
    __syncthreads();
    #pragma unroll
    for (int s = 128; s > 0; s >>= 1) {
        if (tid < s) s_red[tid] += s_red[tid + s];
        __syncthreads();
    }
    if (tid == 0) g_partial[blockIdx.x] = s_red[0];

    // ---- warp-cooperative coalesced one-hot encodings write ----
    // NOTE: out_enc is only 8-byte aligned (base offset 2+Q_ELEMS floats ≡ 8 mod 16),
    // so stores must be float2 (STG.64), never float4.
    if (write_aux) {
        float* enc = out_enc + (size_t)blockIdx.x * TPB * NUM_EMB;
        const int warp = tid >> 5, lane = tid & 31;
        for (int r = warp; r < TPB; r += 8) {
            int kb = s_kmin[r];
            float2* rowp = (float2*)(enc + (size_t)r * NUM_EMB);
            #pragma unroll
            for (int q2 = 0; q2 < 8; q2++) {
                int col = q2 * 64 + lane * 2;            // 256B contiguous per q2 across warp
                float2 v = make_float2(0.f, 0.f);
                unsigned rel = (unsigned)(kb - col);
                if (rel < 2u) ((float*)&v)[rel] = 1.0f;
                rowp[col >> 1] = v;
            }
        }
    }
}

// ---------------- finalize: loss scalar + perplexity ----------------
__global__ void vq_final(float* __restrict__ loss_out, float* __restrict__ perp_out) {
    __shared__ double sh[512];
    const int t = threadIdx.x;

    sh[t] = (double)g_partial[t];
    __syncthreads();
    for (int s = 256; s > 0; s >>= 1) { if (t < s) sh[t] += sh[t + s]; __syncthreads(); }
    if (t == 0) *loss_out = (float)(0.25 * sh[0] / (double)Q_ELEMS);
    __syncthreads();

    {
        double p = (double)g_hist[t] / (double)NPTS;
        sh[t] = p * log(p + 1e-10);
    }
    __syncthreads();
    for (int s = 256; s > 0; s >>= 1) { if (t < s) sh[t] += sh[t + s]; __syncthreads(); }
    if (t == 0) *perp_out = (float)exp(-sh[0]);
}

// ---------------- launch ----------------
extern "C" void kernel_launch(void* const* d_in, const int* in_sizes, int n_in,
                              void* d_out, int out_size) {
    const float* x   = (const float*)d_in[0];
    const float* emb = (const float*)d_in[1];
    float* out = (float*)d_out;

    const bool full = (out_size >= FULL_OUT);
    float* out_loss = full ? out : nullptr;
    float* out_q    = full ? out + 1 : out;             // fallback: quantized-only output
    float* out_perp = full ? out + 1 + Q_ELEMS : nullptr;
    float* out_enc  = full ? out + 2 + Q_ELEMS : nullptr;

    cudaFuncSetAttribute(vq_main, cudaFuncAttributeMaxDynamicSharedMemorySize, SMEM_BYTES);

    vq_init<<<1, 512>>>();
    vq_main<<<NBLK, TPB, SMEM_BYTES>>>(x, emb, out_q, out_enc, full ? 1 : 0);
    if (full) vq_final<<<1, 512>>>(out_loss, out_perp);
}

// round 7
// speedup vs baseline: 1.0192x; 1.0192x over previous
#include <cuda_runtime.h>
#include <math.h>

#define NUM_EMB 512
#define DIM 64
#define NPTS 131072          // 32*64*64 spatial points
#define TPB 256
#define NBLK (NPTS / TPB)    // 512 blocks
#define HW 4096              // 64*64

// Output layout (fp32): [loss(1) | quantized NCHW(8388608) | perplexity(1) | encodings(131072*512)]
#define Q_ELEMS 8388608
#define FULL_OUT 75497474

// Scratch (no allocations allowed). g_hist is zero at load; vq_zero re-zeros it
// after each consume so every graph replay sees a clean histogram.
__device__ float g_partial[NBLK];
__device__ int   g_hist[NUM_EMB];

// ---------------- f32x2 helpers (FFMA2 path, sm_100+) ----------------
__device__ __forceinline__ unsigned long long pack2(float lo, float hi) {
    unsigned long long r;
    asm("mov.b64 %0, {%1, %2};" : "=l"(r) : "f"(lo), "f"(hi));
    return r;
}
__device__ __forceinline__ void unpack2(unsigned long long v, float& lo, float& hi) {
    asm("mov.b64 {%0, %1}, %2;" : "=f"(lo), "=f"(hi) : "l"(v));
}
__device__ __forceinline__ void fma2(unsigned long long& acc, unsigned long long a, unsigned long long b) {
    asm("fma.rn.f32x2 %0, %1, %2, %0;" : "+l"(acc) : "l"(a), "l"(b));
}
__device__ __forceinline__ unsigned long long add2(unsigned long long a, unsigned long long b) {
    unsigned long long r;
    asm("add.rn.f32x2 %0, %1, %2;" : "=l"(r) : "l"(a), "l"(b));
    return r;
}

// ---------------- main kernel ----------------
// SMEM layout (dim-pair packing: s_e[k][d2] = (e_k[2*d2], e_k[2*d2+1])):
//   s_e   : 512 codes * 32 dim-pairs * 8B = 131072 B
//   s_hn  : 512 * 4B   (-0.5*||e_k||^2)
//   s_kmin: 256 * 4B
//   s_red : 256 * 4B
#define SMEM_BYTES (131072 + 2048 + 1024 + 1024)

extern __shared__ unsigned char s_raw[];

__global__ __launch_bounds__(TPB, 1)
void vq_main(const float* __restrict__ x,
             const float* __restrict__ emb,
             float* __restrict__ out_q,
             float* __restrict__ out_enc,
             int write_aux) {
    unsigned long long* s_e = (unsigned long long*)s_raw;    // 512*32 pairs
    float* s_hn  = (float*)(s_e + NUM_EMB * 32);             // 512
    int*   s_kmin = (int*)(s_hn + NUM_EMB);                  // 256
    float* s_red  = (float*)(s_kmin + TPB);                  // 256

    const int tid = threadIdx.x;

    // ---- cooperative fill of dim-pair code table ----
    for (int idx = tid; idx < NUM_EMB * 32; idx += TPB) {
        const float* ep = emb + ((idx >> 5) * DIM) + ((idx & 31) * 2);
        s_e[idx] = pack2(ep[0], ep[1]);
    }
    __syncthreads();

    // ---- per-code half-norms (2 codes per thread) ----
    for (int k = tid; k < NUM_EMB; k += TPB) {
        const unsigned long long* row = s_e + (k << 5);
        float nrm = 0.f;
        #pragma unroll 8
        for (int i = 0; i < 32; i++) {
            float a, b; unpack2(row[i], a, b);
            nrm += a * a + b * b;
        }
        s_hn[k] = -0.5f * nrm;
    }

    // ---- load this thread's point z as 32 dim-pairs (64 regs, no duplication) ----
    const int n = blockIdx.x * TPB + tid;
    const int base = ((n >> 12) << 18) + (n & (HW - 1));   // b*262144 + h*64 + w
    unsigned long long zp[32];
    #pragma unroll
    for (int d2 = 0; d2 < 32; d2++) {
        float a = x[base + ((2 * d2)     << 12)];
        float b = x[base + ((2 * d2 + 1) << 12)];
        zp[d2] = pack2(a, b);
    }
    __syncthreads();

    // ---- argmax over s_k = z.e_k - 0.5||e_k||^2 (== argmin distance; tie -> lowest k) ----
    // 2 codes per outer step, 2 f32x2 chains each -> 4 independent chains.
    float best = -3.4e38f;
    int bestk = 0;
    for (int k = 0; k < NUM_EMB; k += 2) {
        const ulonglong2* eA = (const ulonglong2*)(s_e + (k << 5));
        const ulonglong2* eB = (const ulonglong2*)(s_e + ((k + 1) << 5));
        unsigned long long a0 = pack2(s_hn[k], 0.f),     a1 = 0ull;
        unsigned long long b0 = pack2(s_hn[k + 1], 0.f), b1 = 0ull;
        #pragma unroll
        for (int i = 0; i < 16; i++) {
            ulonglong2 vA = eA[i];
            ulonglong2 vB = eB[i];
            fma2(a0, zp[2 * i],     vA.x);
            fma2(a1, zp[2 * i + 1], vA.y);
            fma2(b0, zp[2 * i],     vB.x);
            fma2(b1, zp[2 * i + 1], vB.y);
        }
        unsigned long long sA = add2(a0, a1);
        unsigned long long sB = add2(b0, b1);
        float lA, hA; unpack2(sA, lA, hA);
        float lB, hB; unpack2(sB, lB, hB);
        float sc0 = lA + hA;
        float sc1 = lB + hB;
        if (sc0 > best) { best = sc0; bestk = k; }
        if (sc1 > best) { best = sc1; bestk = k + 1; }
    }

    s_kmin[tid] = bestk;
    atomicAdd(&g_hist[bestk], 1);   // integer atomics: order-invariant -> deterministic

    // ---- quantized scatter (coalesced per channel) + commitment-loss partial ----
    float lsum = 0.f;
    {
        const unsigned long long* erow = s_e + (bestk << 5);
        #pragma unroll 8
        for (int d2 = 0; d2 < 32; d2++) {
            float e0, e1; unpack2(erow[d2], e0, e1);
            float z0, z1; unpack2(zp[d2], z0, z1);
            float df0 = e0 - z0, df1 = e1 - z1;
            lsum += df0 * df0 + df1 * df1;
            out_q[base + ((2 * d2)     << 12)] = e0;
            out_q[base + ((2 * d2 + 1) << 12)] = e1;
        }
    }

    // ---- deterministic fixed-order block reduction of loss partials ----
    s_red[tid] = lsum;
    __syncthreads();
    #pragma unroll
    for (int s = 128; s > 0; s >>= 1) {
        if (tid < s) s_red[tid] += s_red[tid + s];
        __syncthreads();
    }
    if (tid == 0) g_partial[blockIdx.x] = s_red[0];

    // ---- warp-cooperative coalesced one-hot encodings write ----
    // NOTE: out_enc is only 8-byte aligned (base offset 2+Q_ELEMS floats ≡ 8 mod 16),
    // so stores must be float2 (STG.64), never float4.
    if (write_aux) {
        float* enc = out_enc + (size_t)blockIdx.x * TPB * NUM_EMB;
        const int warp = tid >> 5, lane = tid & 31;
        for (int r = warp; r < TPB; r += 8) {
            int kb = s_kmin[r];
            float2* rowp = (float2*)(enc + (size_t)r * NUM_EMB);
            #pragma unroll
            for (int q2 = 0; q2 < 8; q2++) {
                int col = q2 * 64 + lane * 2;            // 256B contiguous per q2 across warp
                float2 v = make_float2(0.f, 0.f);
                unsigned rel = (unsigned)(kb - col);
                if (rel < 2u) ((float*)&v)[rel] = 1.0f;
                rowp[col >> 1] = v;
            }
        }
    }
}

// ---------------- finalize: loss scalar + perplexity ----------------
__global__ void vq_final(float* __restrict__ loss_out, float* __restrict__ perp_out) {
    __shared__ double sh[512];
    const int t = threadIdx.x;

    sh[t] = (double)g_partial[t];
    __syncthreads();
    for (int s = 256; s > 0; s >>= 1) { if (t < s) sh[t] += sh[t + s]; __syncthreads(); }
    if (t == 0) *loss_out = (float)(0.25 * sh[0] / (double)Q_ELEMS);
    __syncthreads();

    {
        double p = (double)g_hist[t] / (double)NPTS;
        sh[t] = p * log(p + 1e-10);
    }
    __syncthreads();
    for (int s = 256; s > 0; s >>= 1) { if (t < s) sh[t] += sh[t + s]; __syncthreads(); }
    if (t == 0) *perp_out = (float)exp(-sh[0]);
}

// ---------------- zero the histogram for the next replay ----------------
__global__ void vq_zero() {
    g_hist[threadIdx.x] = 0;
}

// ---------------- launch ----------------
// Order (main, final, zero): puts vq_main in ncu's captured slot (index ≡ 0 mod 3),
// and g_hist is consumed before being re-zeroed for the next deterministic replay.
extern "C" void kernel_launch(void* const* d_in, const int* in_sizes, int n_in,
                              void* d_out, int out_size) {
    const float* x   = (const float*)d_in[0];
    const float* emb = (const float*)d_in[1];
    float* out = (float*)d_out;

    const bool full = (out_size >= FULL_OUT);
    float* out_loss = full ? out : nullptr;
    float* out_q    = full ? out + 1 : out;             // fallback: quantized-only output
    float* out_perp = full ? out + 1 + Q_ELEMS : nullptr;
    float* out_enc  = full ? out + 2 + Q_ELEMS : nullptr;

    cudaFuncSetAttribute(vq_main, cudaFuncAttributeMaxDynamicSharedMemorySize, SMEM_BYTES);

    vq_main<<<NBLK, TPB, SMEM_BYTES>>>(x, emb, out_q, out_enc, full ? 1 : 0);
    if (full) vq_final<<<1, 512>>>(out_loss, out_perp);
    vq_zero<<<1, NUM_EMB>>>();
}

// round 12
// speedup vs baseline: 1.2602x; 1.2365x over previous
#include <cuda_runtime.h>
#include <math.h>

#define NUM_EMB 512
#define DIM 64
#define NPTS 131072          // 32*64*64 spatial points
#define TPB 256
#define PPT 2                // points per thread
#define PTS_PER_CTA (TPB * PPT)          // 512
#define NBLK (NPTS / PTS_PER_CTA)        // 256 blocks
#define HW 4096              // 64*64

// Output layout (fp32): [loss(1) | quantized NCHW(8388608) | perplexity(1) | encodings(131072*512)]
#define Q_ELEMS 8388608
#define FULL_OUT 75497474

// Scratch (no allocations allowed). g_hist is zero at load; vq_zero re-zeros it
// after each consume so every graph replay sees a clean histogram.
__device__ float g_partial[NBLK];
__device__ int   g_hist[NUM_EMB];

// ---------------- f32x2 helpers (FFMA2 path, sm_100+) ----------------
__device__ __forceinline__ unsigned long long pack2(float lo, float hi) {
    unsigned long long r;
    asm("mov.b64 %0, {%1, %2};" : "=l"(r) : "f"(lo), "f"(hi));
    return r;
}
__device__ __forceinline__ void unpack2(unsigned long long v, float& lo, float& hi) {
    asm("mov.b64 {%0, %1}, %2;" : "=f"(lo), "=f"(hi) : "l"(v));
}
__device__ __forceinline__ void fma2(unsigned long long& acc, unsigned long long a, unsigned long long b) {
    asm("fma.rn.f32x2 %0, %1, %2, %0;" : "+l"(acc) : "l"(a), "l"(b));
}
__device__ __forceinline__ unsigned long long add2(unsigned long long a, unsigned long long b) {
    unsigned long long r;
    asm("add.rn.f32x2 %0, %1, %2;" : "=l"(r) : "l"(a), "l"(b));
    return r;
}

// ---------------- main kernel ----------------
// SMEM layout (dim-pair packing: s_e[k][d2] = (e_k[2*d2], e_k[2*d2+1])):
//   s_e   : 512 codes * 32 dim-pairs * 8B = 131072 B
//   s_hn  : 512 * 4B   (-0.5*||e_k||^2)
//   s_kmin: 512 * 4B   (one per point in this CTA)
//   s_red : 256 * 4B
#define SMEM_BYTES (131072 + 2048 + 2048 + 1024)

extern __shared__ unsigned char s_raw[];

__global__ __launch_bounds__(TPB, 1)
void vq_main(const float* __restrict__ x,
             const float* __restrict__ emb,
             float* __restrict__ out_q,
             float* __restrict__ out_enc,
             int write_aux) {
    unsigned long long* s_e = (unsigned long long*)s_raw;    // 512*32 pairs
    float* s_hn  = (float*)(s_e + NUM_EMB * 32);             // 512
    int*   s_kmin = (int*)(s_hn + NUM_EMB);                  // 512
    float* s_red  = (float*)(s_kmin + PTS_PER_CTA);          // 256

    const int tid = threadIdx.x;

    // ---- cooperative fill of dim-pair code table ----
    for (int idx = tid; idx < NUM_EMB * 32; idx += TPB) {
        const float* ep = emb + ((idx >> 5) * DIM) + ((idx & 31) * 2);
        s_e[idx] = pack2(ep[0], ep[1]);
    }
    __syncthreads();

    // ---- per-code half-norms (2 codes per thread) ----
    for (int k = tid; k < NUM_EMB; k += TPB) {
        const unsigned long long* row = s_e + (k << 5);
        float nrm = 0.f;
        #pragma unroll 8
        for (int i = 0; i < 32; i++) {
            float a, b; unpack2(row[i], a, b);
            nrm += a * a + b * b;
        }
        s_hn[k] = -0.5f * nrm;
    }

    // ---- load TWO points per thread as dim-pairs (2 * 64 regs) ----
    const int n0 = blockIdx.x * PTS_PER_CTA + tid;
    const int n1 = n0 + TPB;
    const int base0 = ((n0 >> 12) << 18) + (n0 & (HW - 1));
    const int base1 = ((n1 >> 12) << 18) + (n1 & (HW - 1));
    unsigned long long zp0[32], zp1[32];
    #pragma unroll
    for (int d2 = 0; d2 < 32; d2++) {
        zp0[d2] = pack2(x[base0 + ((2 * d2) << 12)], x[base0 + ((2 * d2 + 1) << 12)]);
        zp1[d2] = pack2(x[base1 + ((2 * d2) << 12)], x[base1 + ((2 * d2 + 1) << 12)]);
    }
    __syncthreads();

    // ---- argmax over s_k = z.e_k - 0.5||e_k||^2 for both points ----
    // 2 codes/iter, 2 points -> 8 independent f32x2 chains; each LDS.128 feeds 4 FFMA2.
    float best0 = -3.4e38f, best1 = -3.4e38f;
    int bk0 = 0, bk1 = 0;
    for (int k = 0; k < NUM_EMB; k += 2) {
        const ulonglong2* eA = (const ulonglong2*)(s_e + (k << 5));
        const ulonglong2* eB = (const ulonglong2*)(s_e + ((k + 1) << 5));
        const unsigned long long hA = pack2(s_hn[k], 0.f);
        const unsigned long long hB = pack2(s_hn[k + 1], 0.f);
        unsigned long long c00 = hA, c01 = 0ull, c02 = hB, c03 = 0ull;   // point 0
        unsigned long long c10 = hA, c11 = 0ull, c12 = hB, c13 = 0ull;   // point 1
        #pragma unroll
        for (int i = 0; i < 16; i++) {
            ulonglong2 vA = eA[i];
            ulonglong2 vB = eB[i];
            fma2(c00, zp0[2 * i],     vA.x);
            fma2(c01, zp0[2 * i + 1], vA.y);
            fma2(c02, zp0[2 * i],     vB.x);
            fma2(c03, zp0[2 * i + 1], vB.y);
            fma2(c10, zp1[2 * i],     vA.x);
            fma2(c11, zp1[2 * i + 1], vA.y);
            fma2(c12, zp1[2 * i],     vB.x);
            fma2(c13, zp1[2 * i + 1], vB.y);
        }
        float l, h, sc;
        unpack2(add2(c00, c01), l, h); sc = l + h;
        if (sc > best0) { best0 = sc; bk0 = k; }
        unpack2(add2(c02, c03), l, h); sc = l + h;
        if (sc > best0) { best0 = sc; bk0 = k + 1; }
        unpack2(add2(c10, c11), l, h); sc = l + h;
        if (sc > best1) { best1 = sc; bk1 = k; }
        unpack2(add2(c12, c13), l, h); sc = l + h;
        if (sc > best1) { best1 = sc; bk1 = k + 1; }
    }

    s_kmin[tid]       = bk0;
    s_kmin[tid + TPB] = bk1;
    atomicAdd(&g_hist[bk0], 1);     // int atomics: order-invariant -> deterministic
    atomicAdd(&g_hist[bk1], 1);

    // ---- quantized scatter (coalesced per channel) + commitment-loss partials ----
    float lsum = 0.f;
    {
        const unsigned long long* er0 = s_e + (bk0 << 5);
        const unsigned long long* er1 = s_e + (bk1 << 5);
        #pragma unroll 8
        for (int d2 = 0; d2 < 32; d2++) {
            float e0, e1, z0, z1, d0, d1;
            unpack2(er0[d2], e0, e1); unpack2(zp0[d2], z0, z1);
            d0 = e0 - z0; d1 = e1 - z1; lsum += d0 * d0 + d1 * d1;
            out_q[base0 + ((2 * d2)     << 12)] = e0;
            out_q[base0 + ((2 * d2 + 1) << 12)] = e1;
            unpack2(er1[d2], e0, e1); unpack2(zp1[d2], z0, z1);
            d0 = e0 - z0; d1 = e1 - z1; lsum += d0 * d0 + d1 * d1;
            out_q[base1 + ((2 * d2)     << 12)] = e0;
            out_q[base1 + ((2 * d2 + 1) << 12)] = e1;
        }
    }

    // ---- deterministic fixed-order block reduction of loss partials ----
    s_red[tid] = lsum;
    __syncthreads();
    #pragma unroll
    for (int s = 128; s > 0; s >>= 1) {
        if (tid < s) s_red[tid] += s_red[tid + s];
        __syncthreads();
    }
    if (tid == 0) g_partial[blockIdx.x] = s_red[0];

    // ---- warp-cooperative coalesced one-hot encodings write ----
    // NOTE: out_enc is only 8-byte aligned (base offset 2+Q_ELEMS floats ≡ 8 mod 16),
    // so stores must be float2 (STG.64), never float4.
    if (write_aux) {
        float* enc = out_enc + (size_t)blockIdx.x * PTS_PER_CTA * NUM_EMB;
        const int warp = tid >> 5, lane = tid & 31;
        for (int r = warp; r < PTS_PER_CTA; r += 8) {
            int kb = s_kmin[r];
            float2* rowp = (float2*)(enc + (size_t)r * NUM_EMB);
            #pragma unroll
            for (int q2 = 0; q2 < 8; q2++) {
                int col = q2 * 64 + lane * 2;            // 256B contiguous per q2 across warp
                float2 v = make_float2(0.f, 0.f);
                unsigned rel = (unsigned)(kb - col);
                if (rel < 2u) ((float*)&v)[rel] = 1.0f;
                rowp[col >> 1] = v;
            }
        }
    }
}

// ---------------- finalize: loss scalar + perplexity ----------------
__global__ void vq_final(float* __restrict__ loss_out, float* __restrict__ perp_out) {
    __shared__ double sh[512];
    const int t = threadIdx.x;

    sh[t] = (t < NBLK) ? (double)g_partial[t] : 0.0;
    __syncthreads();
    for (int s = 256; s > 0; s >>= 1) { if (t < s) sh[t] += sh[t + s]; __syncthreads(); }
    if (t == 0) *loss_out = (float)(0.25 * sh[0] / (double)Q_ELEMS);
    __syncthreads();

    {
        double p = (double)g_hist[t] / (double)NPTS;
        sh[t] = p * log(p + 1e-10);
    }
    __syncthreads();
    for (int s = 256; s > 0; s >>= 1) { if (t < s) sh[t] += sh[t + s]; __syncthreads(); }
    if (t == 0) *perp_out = (float)exp(-sh[0]);
}

// ---------------- zero the histogram for the next replay ----------------
__global__ void vq_zero() {
    g_hist[threadIdx.x] = 0;
}

// ---------------- launch ----------------
// Order (main, final, zero): keeps vq_main in ncu's captured slot, and g_hist is
// consumed before being re-zeroed for the next deterministic replay.
extern "C" void kernel_launch(void* const* d_in, const int* in_sizes, int n_in,
                              void* d_out, int out_size) {
    const float* x   = (const float*)d_in[0];
    const float* emb = (const float*)d_in[1];
    float* out = (float*)d_out;

    const bool full = (out_size >= FULL_OUT);
    float* out_loss = full ? out : nullptr;
    float* out_q    = full ? out + 1 : out;             // fallback: quantized-only output
    float* out_perp = full ? out + 1 + Q_ELEMS : nullptr;
    float* out_enc  = full ? out + 2 + Q_ELEMS : nullptr;

    cudaFuncSetAttribute(vq_main, cudaFuncAttributeMaxDynamicSharedMemorySize, SMEM_BYTES);

    vq_main<<<NBLK, TPB, SMEM_BYTES>>>(x, emb, out_q, out_enc, full ? 1 : 0);
    if (full) vq_final<<<1, 512>>>(out_loss, out_perp);
    vq_zero<<<1, NUM_EMB>>>();
}